// round 13
// baseline (speedup 1.0000x reference)
#include <cuda_runtime.h>
#include <cstdint>

#define NMAX 10000
#define EMAX 100000
#define FDIM 128
#define KDIM 16
#define RDIM 8
#define HDIM 64

// ---------------- scratch (static __device__ arrays; no allocation) ----------------
__device__ float g_x[NMAX * FDIM];                 // node_feats @ W_up        (5.1 MB)
__device__ float g_ew[EMAX * KDIM];                // masked weighted edge attrs (6.4 MB)
__device__ float g_agg[(size_t)NMAX * KDIM * FDIM];// aggregated messages, [n][f*16+k] (82 MB)
__device__ float g_wdp[KDIM * FDIM * FDIM];        // permuted W_down (1 MB)
__device__ int   g_counts[NMAX];
__device__ int   g_offsets[NMAX + 1];
__device__ int   g_cursor[NMAX];
__device__ int   g_sorted[EMAX];

typedef unsigned long long ull;

// ---------------- f32x2 packed-FMA helpers (sm_103a) ----------------
__device__ __forceinline__ ull pack2(float x, float y) {
    ull r; asm("mov.b64 %0, {%1, %2};" : "=l"(r) : "f"(x), "f"(y)); return r;
}
__device__ __forceinline__ void unpack2(ull v, float& x, float& y) {
    asm("mov.b64 {%0, %1}, %2;" : "=f"(x), "=f"(y) : "l"(v));
}
__device__ __forceinline__ ull ffma2(ull a, ull b, ull c) {
    ull d; asm("fma.rn.f32x2 %0, %1, %2, %3;" : "=l"(d) : "l"(a), "l"(b), "l"(c)); return d;
}

// ---------------- generic fp32 GEMM:  C[M,128] = scale * A[M,K] @ B[K,128] ----------------
// BM=64, BN=128, BK=16, 256 threads. Microtile 4 rows x 8 cols per thread,
// columns paired for FFMA2: thread (rt,ct) owns rows rt*4..+3, cols {2ct,2ct+1}+32j.
__device__ __forceinline__ void gemm_body(const float* __restrict__ A,
                                          const float* __restrict__ B,
                                          float* __restrict__ C,
                                          int M, int K, float scale)
{
    __shared__ ull As2[16][64];  // (a,a) duplicated pairs, 8 KB
    __shared__ ull Bs[16][64];   // column pairs, 8 KB

    const int tid = threadIdx.x;
    const int rt  = tid >> 4;          // 0..15 row tile
    const int ct  = tid & 15;          // 0..15 col tile
    const int m0  = blockIdx.x * 64;

    // global->smem fill mapping
    const int ar  = tid >> 2;          // 0..63 (A row)
    const int akc = (tid & 3) << 2;    // 0,4,8,12 (A k chunk)
    const int bk  = tid >> 5;          // 0..7 (B k row)
    const int bc  = (tid & 31) << 2;   // B col 0..124 step 4
    const int bc2 = (tid & 31) << 1;   // B float2 col index

    ull acc[4][4];
#pragma unroll
    for (int i = 0; i < 4; i++)
#pragma unroll
        for (int j = 0; j < 4; j++) acc[i][j] = 0ull;

    const int ntiles = K >> 4;
    const int arow   = m0 + ar;

    float4 pa, pb0, pb1;
    // prefetch tile 0
    pa  = (arow < M) ? *(const float4*)(A + (size_t)arow * K + akc)
                     : make_float4(0.f, 0.f, 0.f, 0.f);
    pb0 = *(const float4*)(B + (size_t)bk * 128 + bc);
    pb1 = *(const float4*)(B + (size_t)(bk + 8) * 128 + bc);

    for (int kt = 0; kt < ntiles; ++kt) {
        As2[akc + 0][ar] = pack2(pa.x, pa.x);
        As2[akc + 1][ar] = pack2(pa.y, pa.y);
        As2[akc + 2][ar] = pack2(pa.z, pa.z);
        As2[akc + 3][ar] = pack2(pa.w, pa.w);
        Bs[bk][bc2]         = pack2(pb0.x, pb0.y);
        Bs[bk][bc2 + 1]     = pack2(pb0.z, pb0.w);
        Bs[bk + 8][bc2]     = pack2(pb1.x, pb1.y);
        Bs[bk + 8][bc2 + 1] = pack2(pb1.z, pb1.w);
        __syncthreads();

        if (kt + 1 < ntiles) {   // prefetch next tile (overlaps compute)
            const int k0 = (kt + 1) << 4;
            pa  = (arow < M) ? *(const float4*)(A + (size_t)arow * K + k0 + akc)
                             : make_float4(0.f, 0.f, 0.f, 0.f);
            pb0 = *(const float4*)(B + (size_t)(k0 + bk) * 128 + bc);
            pb1 = *(const float4*)(B + (size_t)(k0 + bk + 8) * 128 + bc);
        }

#pragma unroll
        for (int k = 0; k < 16; ++k) {
            const ull a0 = As2[k][rt * 4 + 0];
            const ull a1 = As2[k][rt * 4 + 1];
            const ull a2 = As2[k][rt * 4 + 2];
            const ull a3 = As2[k][rt * 4 + 3];
            const ull b0 = Bs[k][ct];
            const ull b1 = Bs[k][ct + 16];
            const ull b2 = Bs[k][ct + 32];
            const ull b3 = Bs[k][ct + 48];
            acc[0][0] = ffma2(a0, b0, acc[0][0]); acc[0][1] = ffma2(a0, b1, acc[0][1]);
            acc[0][2] = ffma2(a0, b2, acc[0][2]); acc[0][3] = ffma2(a0, b3, acc[0][3]);
            acc[1][0] = ffma2(a1, b0, acc[1][0]); acc[1][1] = ffma2(a1, b1, acc[1][1]);
            acc[1][2] = ffma2(a1, b2, acc[1][2]); acc[1][3] = ffma2(a1, b3, acc[1][3]);
            acc[2][0] = ffma2(a2, b0, acc[2][0]); acc[2][1] = ffma2(a2, b1, acc[2][1]);
            acc[2][2] = ffma2(a2, b2, acc[2][2]); acc[2][3] = ffma2(a2, b3, acc[2][3]);
            acc[3][0] = ffma2(a3, b0, acc[3][0]); acc[3][1] = ffma2(a3, b1, acc[3][1]);
            acc[3][2] = ffma2(a3, b2, acc[3][2]); acc[3][3] = ffma2(a3, b3, acc[3][3]);
        }
        __syncthreads();
    }

#pragma unroll
    for (int i = 0; i < 4; i++) {
        const int row = m0 + rt * 4 + i;
        if (row < M) {
#pragma unroll
            for (int j = 0; j < 4; j++) {
                float lo, hi; unpack2(acc[i][j], lo, hi);
                *(float2*)(C + (size_t)row * 128 + 2 * ct + 32 * j) =
                    make_float2(lo * scale, hi * scale);
            }
        }
    }
}

__global__ void k_gemm_up(const float* __restrict__ A, const float* __restrict__ B, int M) {
    gemm_body(A, B, g_x, M, FDIM, 1.0f);
}
__global__ void k_gemm_down(float* __restrict__ C, int M) {
    gemm_body(g_agg, g_wdp, C, M, KDIM * FDIM, 0.1f);  // 1/AVG_NUM_NEIGHBORS
}

// ---------------- W_down permutation: row k*128+f  ->  row f*16+k ----------------
__global__ void k_permute(const float* __restrict__ Wd) {
    const int idx = blockIdx.x * 256 + threadIdx.x;
    if (idx >= KDIM * FDIM * FDIM) return;
    const int col = idx & 127;
    const int row = idx >> 7;       // 0..2047 = k*128+f
    const int k   = row >> 7;
    const int f   = row & 127;
    g_wdp[((f << 4) + k) * 128 + col] = Wd[idx];
}

// ---------------- radial MLP + masked edge weighting -> g_ew ----------------
// NOTE: edge_mask arrives as int32 (harness promotes bool -> int32).
__global__ void k_radial(const float* __restrict__ radial,
                         const float* __restrict__ ef,
                         const int* __restrict__ mask,
                         const float* __restrict__ W1,
                         const float* __restrict__ W2,
                         int E)
{
    __shared__ float W1s[RDIM * HDIM];   // 512
    __shared__ float W2s[HDIM * KDIM];   // 1024
    const int tid = threadIdx.x;
    for (int i = tid; i < RDIM * HDIM; i += 256) W1s[i] = W1[i];
    for (int i = tid; i < HDIM * KDIM; i += 256) W2s[i] = W2[i];
    __syncthreads();

    const int e = blockIdx.x * 256 + tid;
    if (e >= E) return;

    float r[8];
    {
        const float4 r0 = *(const float4*)(radial + (size_t)e * 8);
        const float4 r1 = *(const float4*)(radial + (size_t)e * 8 + 4);
        r[0] = r0.x; r[1] = r0.y; r[2] = r0.z; r[3] = r0.w;
        r[4] = r1.x; r[5] = r1.y; r[6] = r1.z; r[7] = r1.w;
    }
    float w[16];
#pragma unroll
    for (int k = 0; k < 16; k++) w[k] = 0.f;

#pragma unroll 4
    for (int j = 0; j < HDIM; j++) {
        float h = 0.f;
#pragma unroll
        for (int i = 0; i < 8; i++) h = fmaf(r[i], W1s[i * HDIM + j], h);
        const float s = __fdividef(h, 1.0f + __expf(-h));   // silu
#pragma unroll
        for (int k = 0; k < 16; k++) w[k] = fmaf(s, W2s[j * 16 + k], w[k]);
    }

    const float m = (mask[e] != 0) ? 1.0f : 0.0f;
    const float4* efp = (const float4*)(ef + (size_t)e * 16);
    float4* op = (float4*)(g_ew + (size_t)e * 16);
#pragma unroll
    for (int q = 0; q < 4; q++) {
        const float4 v = efp[q];
        op[q] = make_float4(m * v.x * w[q * 4 + 0], m * v.y * w[q * 4 + 1],
                            m * v.z * w[q * 4 + 2], m * v.w * w[q * 4 + 3]);
    }
}

// ---------------- counting sort of edges by receiver ----------------
__global__ void k_zero_counts(int n) {
    const int i = blockIdx.x * 256 + threadIdx.x;
    if (i < n) g_counts[i] = 0;
}
__global__ void k_hist(const int* __restrict__ recv, int E) {
    const int e = blockIdx.x * 256 + threadIdx.x;
    if (e < E) atomicAdd(&g_counts[recv[e]], 1);
}
// one block, 1024 threads: exclusive scan of g_counts -> g_offsets (and g_cursor copy)
__global__ void k_scan(int n) {
    __shared__ int wsum[32];
    const int tid  = threadIdx.x;
    const int lane = tid & 31;
    const int wid  = tid >> 5;
    int carry = 0;
    for (int base = 0; base < n; base += 1024) {
        const int i = base + tid;
        const int v = (i < n) ? g_counts[i] : 0;
        int x = v;
#pragma unroll
        for (int off = 1; off < 32; off <<= 1) {
            const int y = __shfl_up_sync(0xffffffffu, x, off);
            if (lane >= off) x += y;
        }
        if (lane == 31) wsum[wid] = x;
        __syncthreads();
        if (wid == 0) {
            int s = wsum[lane];
#pragma unroll
            for (int off = 1; off < 32; off <<= 1) {
                const int y = __shfl_up_sync(0xffffffffu, s, off);
                if (lane >= off) s += y;
            }
            wsum[lane] = s;
        }
        __syncthreads();
        const int wbase = (wid > 0) ? wsum[wid - 1] : 0;
        const int excl  = carry + wbase + x - v;
        if (i < n) { g_offsets[i] = excl; g_cursor[i] = excl; }
        carry += wsum[31];
        __syncthreads();
    }
    if (tid == 0) g_offsets[n] = carry;
}
__global__ void k_scatter(const int* __restrict__ recv, int E) {
    const int e = blockIdx.x * 256 + threadIdx.x;
    if (e < E) {
        const int p = atomicAdd(&g_cursor[recv[e]], 1);
        g_sorted[p] = e;
    }
}

// ---------------- per-receiver aggregation -> g_agg [n][f*16+k] ----------------
__global__ void k_agg(const int* __restrict__ senders) {
    const int n = blockIdx.x;
    const int f = threadIdx.x;     // 128 threads, one output channel each
    const int s0 = g_offsets[n];
    const int s1 = g_offsets[n + 1];
    float acc[16];
#pragma unroll
    for (int k = 0; k < 16; k++) acc[k] = 0.f;

    for (int i = s0; i < s1; ++i) {
        const int e   = g_sorted[i];
        const int snd = __ldg(&senders[e]);
        const float xv = g_x[(size_t)snd * 128 + f];
        const float4* ewp = (const float4*)(g_ew + (size_t)e * 16);
        const float4 e0 = ewp[0], e1 = ewp[1], e2 = ewp[2], e3 = ewp[3];
        acc[0]  = fmaf(e0.x, xv, acc[0]);  acc[1]  = fmaf(e0.y, xv, acc[1]);
        acc[2]  = fmaf(e0.z, xv, acc[2]);  acc[3]  = fmaf(e0.w, xv, acc[3]);
        acc[4]  = fmaf(e1.x, xv, acc[4]);  acc[5]  = fmaf(e1.y, xv, acc[5]);
        acc[6]  = fmaf(e1.z, xv, acc[6]);  acc[7]  = fmaf(e1.w, xv, acc[7]);
        acc[8]  = fmaf(e2.x, xv, acc[8]);  acc[9]  = fmaf(e2.y, xv, acc[9]);
        acc[10] = fmaf(e2.z, xv, acc[10]); acc[11] = fmaf(e2.w, xv, acc[11]);
        acc[12] = fmaf(e3.x, xv, acc[12]); acc[13] = fmaf(e3.y, xv, acc[13]);
        acc[14] = fmaf(e3.z, xv, acc[14]); acc[15] = fmaf(e3.w, xv, acc[15]);
    }

    float4* op = (float4*)(g_agg + (size_t)n * 2048 + f * 16);
    op[0] = make_float4(acc[0],  acc[1],  acc[2],  acc[3]);
    op[1] = make_float4(acc[4],  acc[5],  acc[6],  acc[7]);
    op[2] = make_float4(acc[8],  acc[9],  acc[10], acc[11]);
    op[3] = make_float4(acc[12], acc[13], acc[14], acc[15]);
}

// ---------------- launch ----------------
extern "C" void kernel_launch(void* const* d_in, const int* in_sizes, int n_in,
                              void* d_out, int out_size)
{
    const float* node_feats = (const float*)d_in[0];
    const float* edge_feats = (const float*)d_in[1];
    const float* radial     = (const float*)d_in[2];
    const int*   senders    = (const int*)d_in[3];
    const int*   receivers  = (const int*)d_in[4];
    const int*   mask       = (const int*)d_in[5];   // bool promoted to int32
    const float* W_up       = (const float*)d_in[6];
    const float* W_r1       = (const float*)d_in[7];
    const float* W_r2       = (const float*)d_in[8];
    const float* W_down     = (const float*)d_in[9];

    const int N = in_sizes[0] / FDIM;
    const int E = in_sizes[3];

    k_zero_counts<<<(N + 255) / 256, 256>>>(N);
    k_permute<<<(KDIM * FDIM * FDIM + 255) / 256, 256>>>(W_down);
    k_gemm_up<<<(N + 63) / 64, 256>>>(node_feats, W_up, N);
    k_radial<<<(E + 255) / 256, 256>>>(radial, edge_feats, mask, W_r1, W_r2, E);
    k_hist<<<(E + 255) / 256, 256>>>(receivers, E);
    k_scan<<<1, 1024>>>(N);
    k_scatter<<<(E + 255) / 256, 256>>>(receivers, E);
    k_agg<<<N, 128>>>(senders);
    k_gemm_down<<<(N + 63) / 64, 256>>>((float*)d_out, N);
}